// round 12
// baseline (speedup 1.0000x reference)
#include <cuda_runtime.h>
#include <cuda_bf16.h>
#include <math.h>
#include <stdint.h>

#define BATCH  4
#define NQ     4096
#define NC     1024
#define HEADS  8
#define DH     64
#define INNER  512
#define DX     512
#define DC     768

// ---------------- scratch (static device globals; no allocation) ----------
__device__ uint32_t g_xh[BATCH * NQ * DX / 2],  g_xl[BATCH * NQ * DX / 2];
__device__ uint32_t g_ch[BATCH * NC * DC / 2],  g_cl[BATCH * NC * DC / 2];
__device__ uint32_t g_Wqh[INNER * DX / 2],      g_Wql[INNER * DX / 2];   // [n][kp]
__device__ uint32_t g_Wkh[INNER * DC / 2],      g_Wkl[INNER * DC / 2];
__device__ uint32_t g_Wvh[INNER * DC / 2],      g_Wvl[INNER * DC / 2];
__device__ uint32_t g_Woh[INNER * INNER / 2],   g_Wol[INNER * INNER / 2];
__device__ uint32_t g_Qh[BATCH * HEADS * NQ * 32], g_Ql[BATCH * HEADS * NQ * 32];
__device__ uint32_t g_Kh[BATCH * HEADS * NC * 32], g_Kl[BATCH * HEADS * NC * 32];
__device__ uint32_t g_Vh[BATCH * HEADS * DH * NC / 2], g_Vl[BATCH * HEADS * DH * NC / 2];
__device__ uint32_t g_Ah[BATCH * NQ * 256], g_Al[BATCH * NQ * 256];

// ---------------------------------------------------------------------------
// helpers
// ---------------------------------------------------------------------------
__device__ __forceinline__ void mma16816(float c[4], uint32_t a0, uint32_t a1,
                                         uint32_t a2, uint32_t a3,
                                         uint32_t b0, uint32_t b1)
{
    asm volatile(
        "mma.sync.aligned.m16n8k16.row.col.f32.bf16.bf16.f32 "
        "{%0,%1,%2,%3},{%4,%5,%6,%7},{%8,%9},{%0,%1,%2,%3};"
        : "+f"(c[0]), "+f"(c[1]), "+f"(c[2]), "+f"(c[3])
        : "r"(a0), "r"(a1), "r"(a2), "r"(a3), "r"(b0), "r"(b1));
}

__device__ __forceinline__ void ldsm4(uint32_t* r, uint32_t addr)
{
    asm volatile("ldmatrix.sync.aligned.m8n8.x4.shared.b16 {%0,%1,%2,%3}, [%4];"
                 : "=r"(r[0]), "=r"(r[1]), "=r"(r[2]), "=r"(r[3]) : "r"(addr));
}

__device__ __forceinline__ uint32_t packbf(float lo, float hi)
{
    uint32_t r;
    asm("cvt.rn.bf16x2.f32 %0, %1, %2;" : "=r"(r) : "f"(hi), "f"(lo));
    return r;
}

__device__ __forceinline__ void split_pair(float v0, float v1,
                                           uint32_t& h, uint32_t& l)
{
    h = packbf(v0, v1);
    float h0 = __uint_as_float(h << 16);
    float h1 = __uint_as_float(h & 0xffff0000u);
    l = packbf(v0 - h0, v1 - h1);
}

__device__ __forceinline__ void cp16(uint32_t* s, const uint32_t* g)
{
    uint32_t sa = (uint32_t)__cvta_generic_to_shared(s);
    asm volatile("cp.async.cg.shared.global [%0], [%1], 16;"
                 :: "r"(sa), "l"(g) : "memory");
}
#define CP_COMMIT() asm volatile("cp.async.commit_group;" ::: "memory")
#define CP_WAIT1()  asm volatile("cp.async.wait_group 1;" ::: "memory")
#define CP_WAIT0()  asm volatile("cp.async.wait_group 0;" ::: "memory")

// ---------------------------------------------------------------------------
// pre-conversion kernels
// ---------------------------------------------------------------------------
__global__ __launch_bounds__(256)
void convert_pairs(const float* __restrict__ src, uint32_t* __restrict__ h,
                   uint32_t* __restrict__ l, int n4)
{
    int i = blockIdx.x * 256 + threadIdx.x;
    if (i >= n4) return;
    float4 v = ((const float4*)src)[i];
    uint32_t h0, l0, h1, l1;
    split_pair(v.x, v.y, h0, l0);
    split_pair(v.z, v.w, h1, l1);
    ((uint2*)h)[i] = make_uint2(h0, h1);
    ((uint2*)l)[i] = make_uint2(l0, l1);
}

__global__ __launch_bounds__(256)
void convert_wt2(const float* __restrict__ W0, uint32_t* __restrict__ th0,
                 uint32_t* __restrict__ tl0, const float* __restrict__ W1,
                 uint32_t* __restrict__ th1, uint32_t* __restrict__ tl1, int K)
{
    const float* W = blockIdx.z ? W1 : W0;
    uint32_t* th = blockIdx.z ? th1 : th0;
    uint32_t* tl = blockIdx.z ? tl1 : tl0;
    int n  = blockIdx.y * 256 + threadIdx.x;
    int kp = blockIdx.x;
    float w0 = W[(size_t)(2 * kp) * INNER + n];
    float w1 = W[(size_t)(2 * kp + 1) * INNER + n];
    uint32_t hh, ll;
    split_pair(w0, w1, hh, ll);
    th[(size_t)n * (K / 2) + kp] = hh;
    tl[(size_t)n * (K / 2) + kp] = ll;
}

// ---------------------------------------------------------------------------
// cp.async double-buffered split-bf16 GEMM core, ldmatrix fragment loads.
// CTA 128x128, BK pairs = 16, 256 thr / 8 warps (4m x 2n).
// ---------------------------------------------------------------------------
__device__ __forceinline__ void gemm_core(
    const uint32_t* __restrict__ Ahg, const uint32_t* __restrict__ Alg,
    const uint32_t* __restrict__ Bhg, const uint32_t* __restrict__ Blg,
    uint32_t* smu, int Kp, int row0, int col0, float acc[2][8][4])
{
    const int t = threadIdx.x, lane = t & 31, w = t >> 5;
    const int wm = w & 3, wn = w >> 2;
    const int NT = Kp >> 4;
    const uint32_t smb = (uint32_t)__cvta_generic_to_shared(smu);
    // ldmatrix lane offsets (bytes)
    const uint32_t alane = ((wm * 32 + (lane & 15)) * 20 + 4 * (lane >> 4)) * 4;
    const uint32_t blane = ((wn * 64 + (lane & 7)) * 20 + 4 * (lane >> 3)) * 4;

    auto stage = [&](int s, int kp0) {
        uint32_t* base = smu + s * 10240;
#pragma unroll
        for (int i = 0; i < 2; i++) {
            int e = t + 256 * i, r = e >> 2, c4 = (e & 3) * 4;
            size_t oa = (size_t)(row0 + r) * Kp + kp0 + c4;
            size_t ob = (size_t)(col0 + r) * Kp + kp0 + c4;
            cp16(base + r * 20 + c4,        Ahg + oa);
            cp16(base + 2560 + r * 20 + c4, Alg + oa);
            cp16(base + 5120 + r * 20 + c4, Bhg + ob);
            cp16(base + 7680 + r * 20 + c4, Blg + ob);
        }
        CP_COMMIT();
    };

    stage(0, 0);
    for (int it = 0; it < NT; it++) {
        int cur = it & 1;
        if (it + 1 < NT) { stage(cur ^ 1, (it + 1) * 16); CP_WAIT1(); }
        else             { CP_WAIT0(); }
        __syncthreads();
        const uint32_t sb = smb + cur * 40960;

        uint32_t ah[2][2][4], al[2][2][4];
#pragma unroll
        for (int mf = 0; mf < 2; mf++)
#pragma unroll
            for (int kk = 0; kk < 2; kk++) {
                ldsm4(ah[mf][kk], sb + alane + mf * 1280 + kk * 32);
                ldsm4(al[mf][kk], sb + 10240 + alane + mf * 1280 + kk * 32);
            }
#pragma unroll
        for (int nf = 0; nf < 8; nf++) {
            uint32_t bh[4], bl[4];
            ldsm4(bh, sb + 20480 + blane + nf * 640);
            ldsm4(bl, sb + 30720 + blane + nf * 640);
#pragma unroll
            for (int kk = 0; kk < 2; kk++)
#pragma unroll
                for (int mf = 0; mf < 2; mf++) {
                    uint32_t* A = ah[mf][kk];
                    uint32_t* L = al[mf][kk];
                    mma16816(acc[mf][nf], A[0], A[1], A[2], A[3], bh[2 * kk], bh[2 * kk + 1]);
                    mma16816(acc[mf][nf], A[0], A[1], A[2], A[3], bl[2 * kk], bl[2 * kk + 1]);
                    mma16816(acc[mf][nf], L[0], L[1], L[2], L[3], bh[2 * kk], bh[2 * kk + 1]);
                }
        }
        __syncthreads();
    }
}

// MODE 0: fp32 + bias.  MODE 1: Q split-pairs (scale 1/8).
template <int MODE>
__global__ __launch_bounds__(256, 2)
void hgemm_p(const uint32_t* __restrict__ Ahg, const uint32_t* __restrict__ Alg,
             const uint32_t* __restrict__ Bhg, const uint32_t* __restrict__ Blg,
             float* __restrict__ C, uint32_t* __restrict__ Ph,
             uint32_t* __restrict__ Pl, int K, int SEQ,
             const float* __restrict__ bias)
{
    extern __shared__ uint32_t smu[];
    const int t = threadIdx.x, lane = t & 31, w = t >> 5;
    const int wm = w & 3, wn = w >> 2;
    const int g = lane >> 2, qq = lane & 3;
    const int row0 = blockIdx.y * 128, col0 = blockIdx.x * 128;

    float acc[2][8][4];
#pragma unroll
    for (int mf = 0; mf < 2; mf++)
#pragma unroll
        for (int nf = 0; nf < 8; nf++)
#pragma unroll
            for (int r = 0; r < 4; r++) acc[mf][nf][r] = 0.0f;

    gemm_core(Ahg, Alg, Bhg, Blg, smu, K >> 1, row0, col0, acc);

#pragma unroll
    for (int mf = 0; mf < 2; mf++) {
#pragma unroll
        for (int nf = 0; nf < 8; nf++) {
            int m = row0 + wm * 32 + 16 * mf + g;
            int n = col0 + wn * 64 + 8 * nf + 2 * qq;
            float* c = acc[mf][nf];
            if (MODE == 0) {
                float2 bv = *(const float2*)&bias[n];
                *(float2*)&C[(size_t)m * INNER + n] =
                    make_float2(c[0] + bv.x, c[1] + bv.y);
                *(float2*)&C[(size_t)(m + 8) * INNER + n] =
                    make_float2(c[2] + bv.x, c[3] + bv.y);
            } else {
                int hh_ = n >> 6, d = n & 63;
                int bb = m / SEQ, s = m - bb * SEQ;
                size_t base = ((size_t)(bb * HEADS + hh_) * SEQ + s) * 32 + (d >> 1);
                uint32_t ph, pl;
                split_pair(c[0] * 0.125f, c[1] * 0.125f, ph, pl);
                Ph[base] = ph; Pl[base] = pl;
                split_pair(c[2] * 0.125f, c[3] * 0.125f, ph, pl);
                Ph[base + 8 * 32] = ph; Pl[base + 8 * 32] = pl;
            }
        }
    }
}

// merged K/V projection: blockIdx.z = 0 -> K pairs, 1 -> V^T bf16
__global__ __launch_bounds__(256, 2)
void hgemm_kv(const uint32_t* __restrict__ Ahg, const uint32_t* __restrict__ Alg,
              const uint32_t* __restrict__ Bh0, const uint32_t* __restrict__ Bl0,
              uint32_t* __restrict__ P0h, uint32_t* __restrict__ P0l,
              const uint32_t* __restrict__ Bh1, const uint32_t* __restrict__ Bl1,
              uint32_t* __restrict__ P1h, uint32_t* __restrict__ P1l, int K)
{
    extern __shared__ uint32_t smu[];
    const bool isV = blockIdx.z != 0;
    const uint32_t* Bhg = isV ? Bh1 : Bh0;
    const uint32_t* Blg = isV ? Bl1 : Bl0;
    uint32_t* Ph = isV ? P1h : P0h;
    uint32_t* Pl = isV ? P1l : P0l;

    const int t = threadIdx.x, lane = t & 31, w = t >> 5;
    const int wm = w & 3, wn = w >> 2;
    const int g = lane >> 2, qq = lane & 3;
    const int row0 = blockIdx.y * 128, col0 = blockIdx.x * 128;

    float acc[2][8][4];
#pragma unroll
    for (int mf = 0; mf < 2; mf++)
#pragma unroll
        for (int nf = 0; nf < 8; nf++)
#pragma unroll
            for (int r = 0; r < 4; r++) acc[mf][nf][r] = 0.0f;

    gemm_core(Ahg, Alg, Bhg, Blg, smu, K >> 1, row0, col0, acc);

#pragma unroll
    for (int mf = 0; mf < 2; mf++) {
#pragma unroll
        for (int nf = 0; nf < 8; nf++) {
            int m = row0 + wm * 32 + 16 * mf + g;
            int n = col0 + wn * 64 + 8 * nf + 2 * qq;
            float* c = acc[mf][nf];
            int hh_ = n >> 6, d = n & 63;
            int bb = m / NC, s = m - bb * NC;
            if (!isV) {
                size_t base = ((size_t)(bb * HEADS + hh_) * NC + s) * 32 + (d >> 1);
                uint32_t ph, pl;
                split_pair(c[0], c[1], ph, pl);
                Ph[base] = ph; Pl[base] = pl;
                split_pair(c[2], c[3], ph, pl);
                Ph[base + 8 * 32] = ph; Pl[base + 8 * 32] = pl;
            } else {
                __nv_bfloat16* Vh = (__nv_bfloat16*)Ph;
                __nv_bfloat16* Vl = (__nv_bfloat16*)Pl;
                size_t vb = ((size_t)(bb * HEADS + hh_) * DH + d) * NC + s;
#pragma unroll
                for (int r = 0; r < 4; r++) {
                    size_t a = vb + (size_t)(r & 1) * NC + (r >> 1) * 8;
                    __nv_bfloat16 bh = __float2bfloat16(c[r]);
                    Vh[a] = bh;
                    Vl[a] = __float2bfloat16(c[r] - __bfloat162float(bh));
                }
            }
        }
    }
}

// ---------------------------------------------------------------------------
// Tensor-core attention v4: cp.async double-buffered K/V + ldmatrix frags.
// Dyn smem 110592 B, 2 CTAs/SM.
// ---------------------------------------------------------------------------
__global__ __launch_bounds__(256, 2)
void attn_mma4(const uint32_t* __restrict__ Qhg, const uint32_t* __restrict__ Qlg,
               const uint32_t* __restrict__ Khg, const uint32_t* __restrict__ Klg,
               const uint32_t* __restrict__ Vhg, const uint32_t* __restrict__ Vlg,
               uint32_t* __restrict__ Ah, uint32_t* __restrict__ Al)
{
    extern __shared__ uint32_t sm[];
    uint32_t* Qh = sm;              // 128 x 36 (u32), Ql at +4608

    const int t = threadIdx.x, lane = t & 31, w = t >> 5;
    const int g  = lane >> 2;
    const int qq = lane & 3;
    const int q0 = blockIdx.x * 128;
    const int h  = blockIdx.y;
    const int b  = blockIdx.z;

    const size_t qbase = ((size_t)(b * HEADS + h) * NQ + q0) * 32;
    const size_t kbase = (size_t)(b * HEADS + h) * NC * 32;
    const size_t vbase = (size_t)(b * HEADS + h) * DH * 512;

    const uint32_t smb = (uint32_t)__cvta_generic_to_shared(sm);
    // ldmatrix lane offsets (bytes)
    const uint32_t qlane = ((16 * w + (lane & 15)) * 36 + 4 * (lane >> 4)) * 4;
    const uint32_t nlane = ((lane & 7) * 36 + 4 * (lane >> 3)) * 4;

    auto stageKV = [&](int s, int kt) {
        uint32_t* base = sm + 9216 + s * 9216;
#pragma unroll
        for (int i = 0; i < 2; i++) {
            int e = t + 256 * i, r = e >> 3, c4 = (e & 7) * 4;
            size_t ok = kbase + (size_t)(kt * 64 + r) * 32 + c4;
            size_t ov = vbase + (size_t)r * 512 + kt * 32 + c4;
            cp16(base + r * 36 + c4,        Khg + ok);
            cp16(base + 2304 + r * 36 + c4, Klg + ok);
            cp16(base + 4608 + r * 36 + c4, Vhg + ov);
            cp16(base + 6912 + r * 36 + c4, Vlg + ov);
        }
        CP_COMMIT();
    };

    stageKV(0, 0);

#pragma unroll
    for (int i = 0; i < 4; i++) {
        int e = t + 256 * i;
        int r = e >> 3, c4 = (e & 7) * 4;
        *(uint4*)&Qh[r * 36 + c4] = *(const uint4*)&Qhg[qbase + (size_t)r * 32 + c4];
        *(uint4*)&Qh[4608 + r * 36 + c4] = *(const uint4*)&Qlg[qbase + (size_t)r * 32 + c4];
    }

    float o[8][4];
    float rs[2] = {0.f, 0.f};
#pragma unroll
    for (int j = 0; j < 8; j++)
#pragma unroll
        for (int r = 0; r < 4; r++) o[j][r] = 0.f;

    for (int kt = 0; kt < NC / 64; kt++) {
        int cur = kt & 1;
        if (kt + 1 < NC / 64) { stageKV(cur ^ 1, kt + 1); CP_WAIT1(); }
        else                  { CP_WAIT0(); }
        __syncthreads();
        const uint32_t stg = smb + (9216 + cur * 9216) * 4;   // Kh base (bytes)

        // ---- S = Q K^T ----
        float s[8][4];
#pragma unroll
        for (int j = 0; j < 8; j++)
#pragma unroll
            for (int r = 0; r < 4; r++) s[j][r] = 0.f;

#pragma unroll
        for (int kp = 0; kp < 2; kp++) {
            uint32_t qh0[4], qh1[4], ql0[4], ql1[4];
            ldsm4(qh0, smb + qlane + kp * 64);
            ldsm4(qh1, smb + qlane + kp * 64 + 32);
            ldsm4(ql0, smb + 18432 + qlane + kp * 64);
            ldsm4(ql1, smb + 18432 + qlane + kp * 64 + 32);
#pragma unroll
            for (int j = 0; j < 8; j++) {
                uint32_t kh[4], kl[4];
                ldsm4(kh, stg + nlane + j * 1152 + kp * 64);
                ldsm4(kl, stg + 9216 + nlane + j * 1152 + kp * 64);
                mma16816(s[j], qh0[0], qh0[1], qh0[2], qh0[3], kh[0], kh[1]);
                mma16816(s[j], qh0[0], qh0[1], qh0[2], qh0[3], kl[0], kl[1]);
                mma16816(s[j], ql0[0], ql0[1], ql0[2], ql0[3], kh[0], kh[1]);
                mma16816(s[j], qh1[0], qh1[1], qh1[2], qh1[3], kh[2], kh[3]);
                mma16816(s[j], qh1[0], qh1[1], qh1[2], qh1[3], kl[2], kl[3]);
                mma16816(s[j], ql1[0], ql1[1], ql1[2], ql1[3], kh[2], kh[3]);
            }
        }

        // ---- fused exp + PV ----
        const uint32_t vstg = stg + 18432;   // Vh base (bytes), Vl +9216
#pragma unroll
        for (int kp = 0; kp < 2; kp++) {
            uint32_t aA[4], lA[4], aB[4], lB[4];
            {
                float* s0 = s[4 * kp];
                float* s1 = s[4 * kp + 1];
                float e0 = __expf(s0[0]), e1 = __expf(s0[1]);
                float e2 = __expf(s0[2]), e3 = __expf(s0[3]);
                rs[0] += e0 + e1; rs[1] += e2 + e3;
                split_pair(e0, e1, aA[0], lA[0]);
                split_pair(e2, e3, aA[1], lA[1]);
                e0 = __expf(s1[0]); e1 = __expf(s1[1]);
                e2 = __expf(s1[2]); e3 = __expf(s1[3]);
                rs[0] += e0 + e1; rs[1] += e2 + e3;
                split_pair(e0, e1, aA[2], lA[2]);
                split_pair(e2, e3, aA[3], lA[3]);
            }
            {
                float* s0 = s[4 * kp + 2];
                float* s1 = s[4 * kp + 3];
                float e0 = __expf(s0[0]), e1 = __expf(s0[1]);
                float e2 = __expf(s0[2]), e3 = __expf(s0[3]);
                rs[0] += e0 + e1; rs[1] += e2 + e3;
                split_pair(e0, e1, aB[0], lB[0]);
                split_pair(e2, e3, aB[1], lB[1]);
                e0 = __expf(s1[0]); e1 = __expf(s1[1]);
                e2 = __expf(s1[2]); e3 = __expf(s1[3]);
                rs[0] += e0 + e1; rs[1] += e2 + e3;
                split_pair(e0, e1, aB[2], lB[2]);
                split_pair(e2, e3, aB[3], lB[3]);
            }
#pragma unroll
            for (int j = 0; j < 8; j++) {
                uint32_t vh[4], vl[4];
                ldsm4(vh, vstg + nlane + j * 1152 + kp * 64);
                ldsm4(vl, vstg + 9216 + nlane + j * 1152 + kp * 64);
                mma16816(o[j], aA[0], aA[1], aA[2], aA[3], vh[0], vh[1]);
                mma16816(o[j], aA[0], aA[1], aA[2], aA[3], vl[0], vl[1]);
                mma16816(o[j], lA[0], lA[1], lA[2], lA[3], vh[0], vh[1]);
                mma16816(o[j], aB[0], aB[1], aB[2], aB[3], vh[2], vh[3]);
                mma16816(o[j], aB[0], aB[1], aB[2], aB[3], vl[2], vl[3]);
                mma16816(o[j], lB[0], lB[1], lB[2], lB[3], vh[2], vh[3]);
            }
        }
        __syncthreads();
    }

    rs[0] += __shfl_xor_sync(0xffffffffu, rs[0], 1);
    rs[0] += __shfl_xor_sync(0xffffffffu, rs[0], 2);
    rs[1] += __shfl_xor_sync(0xffffffffu, rs[1], 1);
    rs[1] += __shfl_xor_sync(0xffffffffu, rs[1], 2);
    float inv0 = 1.0f / rs[0], inv1 = 1.0f / rs[1];

#pragma unroll
    for (int j = 0; j < 8; j++) {
        uint32_t hh, ll;
        size_t r1 = (size_t)(b * NQ + q0 + 16 * w + g) * 256 + h * 32 + 4 * j + qq;
        split_pair(o[j][0] * inv0, o[j][1] * inv0, hh, ll);
        Ah[r1] = hh; Al[r1] = ll;
        split_pair(o[j][2] * inv1, o[j][3] * inv1, hh, ll);
        Ah[r1 + 8 * 256] = hh; Al[r1 + 8 * 256] = ll;
    }
}

// ---------------------------------------------------------------------------
extern "C" void kernel_launch(void* const* d_in, const int* in_sizes, int n_in,
                              void* d_out, int out_size)
{
    const float* x   = (const float*)d_in[0];
    const float* ctx = (const float*)d_in[1];
    const float* Wq  = (const float*)d_in[2];
    const float* Wk  = (const float*)d_in[3];
    const float* Wv  = (const float*)d_in[4];
    const float* Wo  = (const float*)d_in[5];
    const float* bo  = (const float*)d_in[6];
    float* out = (float*)d_out;

    uint32_t *xh, *xl, *ch, *cl, *wqh, *wql, *wkh, *wkl, *wvh, *wvl, *woh, *wol;
    uint32_t *qh, *ql, *kh, *kl, *vh, *vl, *ah, *al;
    cudaGetSymbolAddress((void**)&xh, g_xh);   cudaGetSymbolAddress((void**)&xl, g_xl);
    cudaGetSymbolAddress((void**)&ch, g_ch);   cudaGetSymbolAddress((void**)&cl, g_cl);
    cudaGetSymbolAddress((void**)&wqh, g_Wqh); cudaGetSymbolAddress((void**)&wql, g_Wql);
    cudaGetSymbolAddress((void**)&wkh, g_Wkh); cudaGetSymbolAddress((void**)&wkl, g_Wkl);
    cudaGetSymbolAddress((void**)&wvh, g_Wvh); cudaGetSymbolAddress((void**)&wvl, g_Wvl);
    cudaGetSymbolAddress((void**)&woh, g_Woh); cudaGetSymbolAddress((void**)&wol, g_Wol);
    cudaGetSymbolAddress((void**)&qh, g_Qh);   cudaGetSymbolAddress((void**)&ql, g_Ql);
    cudaGetSymbolAddress((void**)&kh, g_Kh);   cudaGetSymbolAddress((void**)&kl, g_Kl);
    cudaGetSymbolAddress((void**)&vh, g_Vh);   cudaGetSymbolAddress((void**)&vl, g_Vl);
    cudaGetSymbolAddress((void**)&ah, g_Ah);   cudaGetSymbolAddress((void**)&al, g_Al);

    cudaFuncSetAttribute(attn_mma4,
                         cudaFuncAttributeMaxDynamicSharedMemorySize, 110592);
    cudaFuncSetAttribute(hgemm_p<0>,
                         cudaFuncAttributeMaxDynamicSharedMemorySize, 81920);
    cudaFuncSetAttribute(hgemm_p<1>,
                         cudaFuncAttributeMaxDynamicSharedMemorySize, 81920);
    cudaFuncSetAttribute(hgemm_kv,
                         cudaFuncAttributeMaxDynamicSharedMemorySize, 81920);

    dim3 blk(256);

    convert_pairs<<<(BATCH * NQ * DX / 4 + 255) / 256, blk>>>(x, xh, xl, BATCH * NQ * DX / 4);
    convert_pairs<<<(BATCH * NC * DC / 4 + 255) / 256, blk>>>(ctx, ch, cl, BATCH * NC * DC / 4);
    convert_wt2<<<dim3(DX / 2, 2, 2), blk>>>(Wq, wqh, wql, Wo, woh, wol, DX);
    convert_wt2<<<dim3(DC / 2, 2, 2), blk>>>(Wk, wkh, wkl, Wv, wvh, wvl, DC);

    hgemm_p<1><<<dim3(4, (BATCH * NQ) / 128), blk, 81920>>>(
        xh, xl, wqh, wql, nullptr, qh, ql, DX, NQ, nullptr);
    hgemm_kv<<<dim3(4, (BATCH * NC) / 128, 2), blk, 81920>>>(
        ch, cl, wkh, wkl, kh, kl, wvh, wvl, vh, vl, DC);

    attn_mma4<<<dim3(NQ / 128, HEADS, BATCH), blk, 110592>>>(
        qh, ql, kh, kl, vh, vl, ah, al);

    hgemm_p<0><<<dim3(4, (BATCH * NQ) / 128), blk, 81920>>>(
        ah, al, woh, wol, out, nullptr, nullptr, INNER, NQ, bo);

    (void)in_sizes; (void)n_in; (void)out_size;
}

// round 13
// speedup vs baseline: 1.0485x; 1.0485x over previous
#include <cuda_runtime.h>
#include <cuda_bf16.h>
#include <math.h>
#include <stdint.h>

#define BATCH  4
#define NQ     4096
#define NC     1024
#define HEADS  8
#define DH     64
#define INNER  512
#define DX     512
#define DC     768

// ---------------- scratch (static device globals; no allocation) ----------
__device__ uint32_t g_xh[BATCH * NQ * DX / 2],  g_xl[BATCH * NQ * DX / 2];
__device__ uint32_t g_ch[BATCH * NC * DC / 2],  g_cl[BATCH * NC * DC / 2];
__device__ uint32_t g_Wqh[INNER * DX / 2],      g_Wql[INNER * DX / 2];   // [n][kp]
__device__ uint32_t g_Wkh[INNER * DC / 2],      g_Wkl[INNER * DC / 2];
__device__ uint32_t g_Wvh[INNER * DC / 2],      g_Wvl[INNER * DC / 2];
__device__ uint32_t g_Woh[INNER * INNER / 2],   g_Wol[INNER * INNER / 2];
__device__ uint32_t g_Qh[BATCH * HEADS * NQ * 32], g_Ql[BATCH * HEADS * NQ * 32];
__device__ uint32_t g_Kh[BATCH * HEADS * NC * 32], g_Kl[BATCH * HEADS * NC * 32];
__device__ uint32_t g_Vh[BATCH * HEADS * DH * NC / 2], g_Vl[BATCH * HEADS * DH * NC / 2];
__device__ uint32_t g_Ah[BATCH * NQ * 256], g_Al[BATCH * NQ * 256];

// ---------------------------------------------------------------------------
// helpers
// ---------------------------------------------------------------------------
__device__ __forceinline__ void mma16816(float c[4], uint32_t a0, uint32_t a1,
                                         uint32_t a2, uint32_t a3,
                                         uint32_t b0, uint32_t b1)
{
    asm volatile(
        "mma.sync.aligned.m16n8k16.row.col.f32.bf16.bf16.f32 "
        "{%0,%1,%2,%3},{%4,%5,%6,%7},{%8,%9},{%0,%1,%2,%3};"
        : "+f"(c[0]), "+f"(c[1]), "+f"(c[2]), "+f"(c[3])
        : "r"(a0), "r"(a1), "r"(a2), "r"(a3), "r"(b0), "r"(b1));
}

__device__ __forceinline__ uint32_t packbf(float lo, float hi)
{
    uint32_t r;
    asm("cvt.rn.bf16x2.f32 %0, %1, %2;" : "=r"(r) : "f"(hi), "f"(lo));
    return r;
}

__device__ __forceinline__ void split_pair(float v0, float v1,
                                           uint32_t& h, uint32_t& l)
{
    h = packbf(v0, v1);
    float h0 = __uint_as_float(h << 16);
    float h1 = __uint_as_float(h & 0xffff0000u);
    l = packbf(v0 - h0, v1 - h1);
}

__device__ __forceinline__ void cp16(uint32_t* s, const uint32_t* g)
{
    uint32_t sa = (uint32_t)__cvta_generic_to_shared(s);
    asm volatile("cp.async.cg.shared.global [%0], [%1], 16;"
                 :: "r"(sa), "l"(g) : "memory");
}
#define CP_COMMIT() asm volatile("cp.async.commit_group;" ::: "memory")
#define CP_WAIT1()  asm volatile("cp.async.wait_group 1;" ::: "memory")
#define CP_WAIT0()  asm volatile("cp.async.wait_group 0;" ::: "memory")

// ---------------------------------------------------------------------------
// single fused pre-conversion kernel: x, ctx pairs + 4 transposed weights.
// grid segments: [0,8192) x | [8192,11264) ctx | [11264,13824) weights.
// ---------------------------------------------------------------------------
__global__ __launch_bounds__(256)
void convert_all(const float* __restrict__ x, const float* __restrict__ ctx,
                 const float* __restrict__ Wq, const float* __restrict__ Wk,
                 const float* __restrict__ Wv, const float* __restrict__ Wo,
                 uint32_t* __restrict__ xh, uint32_t* __restrict__ xl,
                 uint32_t* __restrict__ ch, uint32_t* __restrict__ cl,
                 uint32_t* __restrict__ wqh, uint32_t* __restrict__ wql,
                 uint32_t* __restrict__ wkh, uint32_t* __restrict__ wkl,
                 uint32_t* __restrict__ wvh, uint32_t* __restrict__ wvl,
                 uint32_t* __restrict__ woh, uint32_t* __restrict__ wol)
{
    const int t = threadIdx.x;
    int bid = blockIdx.x;
    if (bid < 11264) {
        const float* src = (bid < 8192) ? x : ctx;
        uint32_t* h = (bid < 8192) ? xh : ch;
        uint32_t* l = (bid < 8192) ? xl : cl;
        int i = (bid < 8192 ? bid : bid - 8192) * 256 + t;
        float4 v = ((const float4*)src)[i];
        uint32_t h0, l0, h1, l1;
        split_pair(v.x, v.y, h0, l0);
        split_pair(v.z, v.w, h1, l1);
        ((uint2*)h)[i] = make_uint2(h0, h1);
        ((uint2*)l)[i] = make_uint2(l0, l1);
    } else {
        int e = bid - 11264;
        const float* W; uint32_t *th, *tl; int K;
        if (e < 512)       { W = Wq; th = wqh; tl = wql; K = DX; }
        else if (e < 1024) { e -= 512;  W = Wo; th = woh; tl = wol; K = INNER; }
        else if (e < 1792) { e -= 1024; W = Wk; th = wkh; tl = wkl; K = DC; }
        else               { e -= 1792; W = Wv; th = wvh; tl = wvl; K = DC; }
        int kp = e >> 1;
        int n  = (e & 1) * 256 + t;
        float w0 = W[(size_t)(2 * kp) * INNER + n];
        float w1 = W[(size_t)(2 * kp + 1) * INNER + n];
        uint32_t hh, ll;
        split_pair(w0, w1, hh, ll);
        th[(size_t)n * (K / 2) + kp] = hh;
        tl[(size_t)n * (K / 2) + kp] = ll;
    }
}

// ---------------------------------------------------------------------------
// cp.async double-buffered split-bf16 GEMM core (R10 proven: scalar LDS).
// CTA 128x128, BK pairs = 16, 256 thr / 8 warps (4m x 2n).
// ---------------------------------------------------------------------------
__device__ __forceinline__ void gemm_core(
    const uint32_t* __restrict__ Ahg, const uint32_t* __restrict__ Alg,
    const uint32_t* __restrict__ Bhg, const uint32_t* __restrict__ Blg,
    uint32_t* smu, int Kp, int row0, int col0, float acc[2][8][4])
{
    const int t = threadIdx.x, lane = t & 31, w = t >> 5;
    const int wm = w & 3, wn = w >> 2;
    const int g = lane >> 2, qq = lane & 3;
    const int NT = Kp >> 4;

    auto stage = [&](int s, int kp0) {
        uint32_t* base = smu + s * 10240;
#pragma unroll
        for (int i = 0; i < 2; i++) {
            int e = t + 256 * i, r = e >> 2, c4 = (e & 3) * 4;
            size_t oa = (size_t)(row0 + r) * Kp + kp0 + c4;
            size_t ob = (size_t)(col0 + r) * Kp + kp0 + c4;
            cp16(base + r * 20 + c4,        Ahg + oa);
            cp16(base + 2560 + r * 20 + c4, Alg + oa);
            cp16(base + 5120 + r * 20 + c4, Bhg + ob);
            cp16(base + 7680 + r * 20 + c4, Blg + ob);
        }
        CP_COMMIT();
    };

    stage(0, 0);
    for (int it = 0; it < NT; it++) {
        int cur = it & 1;
        if (it + 1 < NT) { stage(cur ^ 1, (it + 1) * 16); CP_WAIT1(); }
        else             { CP_WAIT0(); }
        __syncthreads();
        uint32_t* Ahs = smu + cur * 10240;
        uint32_t* Als = Ahs + 2560;
        uint32_t* Bhs = Ahs + 5120;
        uint32_t* Bls = Ahs + 7680;
#pragma unroll
        for (int kk = 0; kk < 2; kk++) {
            const int c0 = 8 * kk + qq;
            uint32_t ah[2][4], al[2][4];
#pragma unroll
            for (int mf = 0; mf < 2; mf++) {
                int r = wm * 32 + 16 * mf + g;
                ah[mf][0] = Ahs[r * 20 + c0];     ah[mf][1] = Ahs[(r + 8) * 20 + c0];
                ah[mf][2] = Ahs[r * 20 + c0 + 4]; ah[mf][3] = Ahs[(r + 8) * 20 + c0 + 4];
                al[mf][0] = Als[r * 20 + c0];     al[mf][1] = Als[(r + 8) * 20 + c0];
                al[mf][2] = Als[r * 20 + c0 + 4]; al[mf][3] = Als[(r + 8) * 20 + c0 + 4];
            }
#pragma unroll
            for (int nf = 0; nf < 8; nf++) {
                int n = wn * 64 + 8 * nf + g;
                uint32_t bh0 = Bhs[n * 20 + c0], bh1 = Bhs[n * 20 + c0 + 4];
                uint32_t bl0 = Bls[n * 20 + c0], bl1 = Bls[n * 20 + c0 + 4];
#pragma unroll
                for (int mf = 0; mf < 2; mf++) {
                    mma16816(acc[mf][nf], ah[mf][0], ah[mf][1], ah[mf][2], ah[mf][3], bh0, bh1);
                    mma16816(acc[mf][nf], ah[mf][0], ah[mf][1], ah[mf][2], ah[mf][3], bl0, bl1);
                    mma16816(acc[mf][nf], al[mf][0], al[mf][1], al[mf][2], al[mf][3], bh0, bh1);
                }
            }
        }
        __syncthreads();
    }
}

// ---------------------------------------------------------------------------
// fused QKV projection: 1D grid of 768 CTAs.
// bid < 512: Q tile (scale 1/8 pairs). else K (pairs) / V (V^T bf16).
// ---------------------------------------------------------------------------
__global__ __launch_bounds__(256, 2)
void proj_all(const uint32_t* __restrict__ xh, const uint32_t* __restrict__ xl,
              const uint32_t* __restrict__ ch, const uint32_t* __restrict__ cl,
              const uint32_t* __restrict__ wqh, const uint32_t* __restrict__ wql,
              const uint32_t* __restrict__ wkh, const uint32_t* __restrict__ wkl,
              const uint32_t* __restrict__ wvh, const uint32_t* __restrict__ wvl,
              uint32_t* __restrict__ qh, uint32_t* __restrict__ ql,
              uint32_t* __restrict__ kh, uint32_t* __restrict__ kl,
              uint32_t* __restrict__ vh, uint32_t* __restrict__ vl)
{
    extern __shared__ uint32_t smu[];
    const int bid = blockIdx.x;
    const bool isQ = bid < 512;
    const int e2 = isQ ? bid : ((bid - 512) & 127);
    const bool isV = !isQ && (bid - 512) >= 128;
    const int row0 = (e2 >> 2) * 128, col0 = (e2 & 3) * 128;
    const int K   = isQ ? DX : DC;
    const int SEQ = isQ ? NQ : NC;
    const uint32_t* Ahg = isQ ? xh : ch;
    const uint32_t* Alg = isQ ? xl : cl;
    const uint32_t* Bhg = isQ ? wqh : (isV ? wvh : wkh);
    const uint32_t* Blg = isQ ? wql : (isV ? wvl : wkl);

    const int t = threadIdx.x, lane = t & 31, w = t >> 5;
    const int wm = w & 3, wn = w >> 2;
    const int g = lane >> 2, qq = lane & 3;

    float acc[2][8][4];
#pragma unroll
    for (int mf = 0; mf < 2; mf++)
#pragma unroll
        for (int nf = 0; nf < 8; nf++)
#pragma unroll
            for (int r = 0; r < 4; r++) acc[mf][nf][r] = 0.0f;

    gemm_core(Ahg, Alg, Bhg, Blg, smu, K >> 1, row0, col0, acc);

    const float scale = isQ ? 0.125f : 1.0f;
    uint32_t* Ph = isQ ? qh : (isV ? vh : kh);
    uint32_t* Pl = isQ ? ql : (isV ? vl : kl);

#pragma unroll
    for (int mf = 0; mf < 2; mf++) {
#pragma unroll
        for (int nf = 0; nf < 8; nf++) {
            int m = row0 + wm * 32 + 16 * mf + g;
            int n = col0 + wn * 64 + 8 * nf + 2 * qq;
            float* c = acc[mf][nf];
            int hh_ = n >> 6, d = n & 63;
            int bb = m / SEQ, s = m - bb * SEQ;
            if (!isV) {
                size_t base = ((size_t)(bb * HEADS + hh_) * SEQ + s) * 32 + (d >> 1);
                uint32_t ph, pl;
                split_pair(c[0] * scale, c[1] * scale, ph, pl);
                Ph[base] = ph; Pl[base] = pl;
                split_pair(c[2] * scale, c[3] * scale, ph, pl);
                Ph[base + 8 * 32] = ph; Pl[base + 8 * 32] = pl;
            } else {
                __nv_bfloat16* Vh = (__nv_bfloat16*)Ph;
                __nv_bfloat16* Vl = (__nv_bfloat16*)Pl;
                size_t vb = ((size_t)(bb * HEADS + hh_) * DH + d) * NC + s;
#pragma unroll
                for (int r = 0; r < 4; r++) {
                    size_t a = vb + (size_t)(r & 1) * NC + (r >> 1) * 8;
                    __nv_bfloat16 bh = __float2bfloat16(c[r]);
                    Vh[a] = bh;
                    Vl[a] = __float2bfloat16(c[r] - __bfloat162float(bh));
                }
            }
        }
    }
}

// ---------------------------------------------------------------------------
// output GEMM: fp32 + bias (R10 proven)
// ---------------------------------------------------------------------------
__global__ __launch_bounds__(256, 2)
void hgemm_out(const uint32_t* __restrict__ Ahg, const uint32_t* __restrict__ Alg,
               const uint32_t* __restrict__ Bhg, const uint32_t* __restrict__ Blg,
               float* __restrict__ C, int K, const float* __restrict__ bias)
{
    extern __shared__ uint32_t smu[];
    const int t = threadIdx.x, lane = t & 31, w = t >> 5;
    const int wm = w & 3, wn = w >> 2;
    const int g = lane >> 2, qq = lane & 3;
    const int row0 = blockIdx.y * 128, col0 = blockIdx.x * 128;

    float acc[2][8][4];
#pragma unroll
    for (int mf = 0; mf < 2; mf++)
#pragma unroll
        for (int nf = 0; nf < 8; nf++)
#pragma unroll
            for (int r = 0; r < 4; r++) acc[mf][nf][r] = 0.0f;

    gemm_core(Ahg, Alg, Bhg, Blg, smu, K >> 1, row0, col0, acc);

#pragma unroll
    for (int mf = 0; mf < 2; mf++) {
#pragma unroll
        for (int nf = 0; nf < 8; nf++) {
            int m = row0 + wm * 32 + 16 * mf + g;
            int n = col0 + wn * 64 + 8 * nf + 2 * qq;
            float* c = acc[mf][nf];
            float2 bv = *(const float2*)&bias[n];
            *(float2*)&C[(size_t)m * INNER + n] =
                make_float2(c[0] + bv.x, c[1] + bv.y);
            *(float2*)&C[(size_t)(m + 8) * INNER + n] =
                make_float2(c[2] + bv.x, c[3] + bv.y);
        }
    }
}

// ---------------------------------------------------------------------------
// Tensor-core attention (R10 proven): cp.async double-buffered K/V,
// fused exp+PV. Dyn smem 110592 B, 2 CTAs/SM.
// ---------------------------------------------------------------------------
__global__ __launch_bounds__(256, 2)
void attn_mma3(const uint32_t* __restrict__ Qhg, const uint32_t* __restrict__ Qlg,
               const uint32_t* __restrict__ Khg, const uint32_t* __restrict__ Klg,
               const uint32_t* __restrict__ Vhg, const uint32_t* __restrict__ Vlg,
               uint32_t* __restrict__ Ah, uint32_t* __restrict__ Al)
{
    extern __shared__ uint32_t sm[];
    uint32_t* Qh = sm;              // 128 x 36
    uint32_t* Ql = sm + 4608;

    const int t = threadIdx.x, lane = t & 31, w = t >> 5;
    const int g  = lane >> 2;
    const int qq = lane & 3;
    const int q0 = blockIdx.x * 128;
    const int h  = blockIdx.y;
    const int b  = blockIdx.z;

    const size_t qbase = ((size_t)(b * HEADS + h) * NQ + q0) * 32;
    const size_t kbase = (size_t)(b * HEADS + h) * NC * 32;
    const size_t vbase = (size_t)(b * HEADS + h) * DH * 512;

    auto stageKV = [&](int s, int kt) {
        uint32_t* base = sm + 9216 + s * 9216;
#pragma unroll
        for (int i = 0; i < 2; i++) {
            int e = t + 256 * i, r = e >> 3, c4 = (e & 7) * 4;
            size_t ok = kbase + (size_t)(kt * 64 + r) * 32 + c4;
            size_t ov = vbase + (size_t)r * 512 + kt * 32 + c4;
            cp16(base + r * 36 + c4,        Khg + ok);
            cp16(base + 2304 + r * 36 + c4, Klg + ok);
            cp16(base + 4608 + r * 36 + c4, Vhg + ov);
            cp16(base + 6912 + r * 36 + c4, Vlg + ov);
        }
        CP_COMMIT();
    };

    stageKV(0, 0);

#pragma unroll
    for (int i = 0; i < 4; i++) {
        int e = t + 256 * i;
        int r = e >> 3, c4 = (e & 7) * 4;
        *(uint4*)&Qh[r * 36 + c4] = *(const uint4*)&Qhg[qbase + (size_t)r * 32 + c4];
        *(uint4*)&Ql[r * 36 + c4] = *(const uint4*)&Qlg[qbase + (size_t)r * 32 + c4];
    }

    float o[8][4];
    float rs[2] = {0.f, 0.f};
#pragma unroll
    for (int j = 0; j < 8; j++)
#pragma unroll
        for (int r = 0; r < 4; r++) o[j][r] = 0.f;

    const int r0 = 16 * w + g;

    for (int kt = 0; kt < NC / 64; kt++) {
        int cur = kt & 1;
        if (kt + 1 < NC / 64) { stageKV(cur ^ 1, kt + 1); CP_WAIT1(); }
        else                  { CP_WAIT0(); }
        __syncthreads();
        uint32_t* Kh = sm + 9216 + cur * 9216;
        uint32_t* Kl = Kh + 2304;
        uint32_t* Vh = Kh + 4608;
        uint32_t* Vl = Kh + 6912;

        float s[8][4];
#pragma unroll
        for (int j = 0; j < 8; j++)
#pragma unroll
            for (int r = 0; r < 4; r++) s[j][r] = 0.f;

#pragma unroll
        for (int kk = 0; kk < 4; kk++) {
            int c0 = qq + 8 * kk;
            uint32_t qh0 = Qh[r0 * 36 + c0],       qh1 = Qh[(r0 + 8) * 36 + c0];
            uint32_t qh2 = Qh[r0 * 36 + c0 + 4],   qh3 = Qh[(r0 + 8) * 36 + c0 + 4];
            uint32_t ql0 = Ql[r0 * 36 + c0],       ql1 = Ql[(r0 + 8) * 36 + c0];
            uint32_t ql2 = Ql[r0 * 36 + c0 + 4],   ql3 = Ql[(r0 + 8) * 36 + c0 + 4];
#pragma unroll
            for (int j = 0; j < 8; j++) {
                int key = 8 * j + g;
                uint32_t kh0 = Kh[key * 36 + c0], kh1 = Kh[key * 36 + c0 + 4];
                uint32_t kl0 = Kl[key * 36 + c0], kl1 = Kl[key * 36 + c0 + 4];
                mma16816(s[j], qh0, qh1, qh2, qh3, kh0, kh1);
                mma16816(s[j], qh0, qh1, qh2, qh3, kl0, kl1);
                mma16816(s[j], ql0, ql1, ql2, ql3, kh0, kh1);
            }
        }

#pragma unroll
        for (int kk = 0; kk < 4; kk++) {
            uint32_t a0, a1, a2, a3, l0, l1, l2, l3;
            {
                float* sj = s[2 * kk];
                float e0 = __expf(sj[0]), e1 = __expf(sj[1]);
                float e2 = __expf(sj[2]), e3 = __expf(sj[3]);
                rs[0] += e0 + e1; rs[1] += e2 + e3;
                split_pair(e0, e1, a0, l0);
                split_pair(e2, e3, a1, l1);
            }
            {
                float* sj = s[2 * kk + 1];
                float e0 = __expf(sj[0]), e1 = __expf(sj[1]);
                float e2 = __expf(sj[2]), e3 = __expf(sj[3]);
                rs[0] += e0 + e1; rs[1] += e2 + e3;
                split_pair(e0, e1, a2, l2);
                split_pair(e2, e3, a3, l3);
            }
            int cp = qq + 8 * kk;
#pragma unroll
            for (int j = 0; j < 8; j++) {
                int d = 8 * j + g;
                uint32_t vh0 = Vh[d * 36 + cp], vh1 = Vh[d * 36 + cp + 4];
                uint32_t vl0 = Vl[d * 36 + cp], vl1 = Vl[d * 36 + cp + 4];
                mma16816(o[j], a0, a1, a2, a3, vh0, vh1);
                mma16816(o[j], a0, a1, a2, a3, vl0, vl1);
                mma16816(o[j], l0, l1, l2, l3, vh0, vh1);
            }
        }
        __syncthreads();
    }

    rs[0] += __shfl_xor_sync(0xffffffffu, rs[0], 1);
    rs[0] += __shfl_xor_sync(0xffffffffu, rs[0], 2);
    rs[1] += __shfl_xor_sync(0xffffffffu, rs[1], 1);
    rs[1] += __shfl_xor_sync(0xffffffffu, rs[1], 2);
    float inv0 = 1.0f / rs[0], inv1 = 1.0f / rs[1];

#pragma unroll
    for (int j = 0; j < 8; j++) {
        uint32_t hh, ll;
        size_t r1 = (size_t)(b * NQ + q0 + 16 * w + g) * 256 + h * 32 + 4 * j + qq;
        split_pair(o[j][0] * inv0, o[j][1] * inv0, hh, ll);
        Ah[r1] = hh; Al[r1] = ll;
        split_pair(o[j][2] * inv1, o[j][3] * inv1, hh, ll);
        Ah[r1 + 8 * 256] = hh; Al[r1 + 8 * 256] = ll;
    }
}

// ---------------------------------------------------------------------------
extern "C" void kernel_launch(void* const* d_in, const int* in_sizes, int n_in,
                              void* d_out, int out_size)
{
    const float* x   = (const float*)d_in[0];
    const float* ctx = (const float*)d_in[1];
    const float* Wq  = (const float*)d_in[2];
    const float* Wk  = (const float*)d_in[3];
    const float* Wv  = (const float*)d_in[4];
    const float* Wo  = (const float*)d_in[5];
    const float* bo  = (const float*)d_in[6];
    float* out = (float*)d_out;

    uint32_t *xh, *xl, *ch, *cl, *wqh, *wql, *wkh, *wkl, *wvh, *wvl, *woh, *wol;
    uint32_t *qh, *ql, *kh, *kl, *vh, *vl, *ah, *al;
    cudaGetSymbolAddress((void**)&xh, g_xh);   cudaGetSymbolAddress((void**)&xl, g_xl);
    cudaGetSymbolAddress((void**)&ch, g_ch);   cudaGetSymbolAddress((void**)&cl, g_cl);
    cudaGetSymbolAddress((void**)&wqh, g_Wqh); cudaGetSymbolAddress((void**)&wql, g_Wql);
    cudaGetSymbolAddress((void**)&wkh, g_Wkh); cudaGetSymbolAddress((void**)&wkl, g_Wkl);
    cudaGetSymbolAddress((void**)&wvh, g_Wvh); cudaGetSymbolAddress((void**)&wvl, g_Wvl);
    cudaGetSymbolAddress((void**)&woh, g_Woh); cudaGetSymbolAddress((void**)&wol, g_Wol);
    cudaGetSymbolAddress((void**)&qh, g_Qh);   cudaGetSymbolAddress((void**)&ql, g_Ql);
    cudaGetSymbolAddress((void**)&kh, g_Kh);   cudaGetSymbolAddress((void**)&kl, g_Kl);
    cudaGetSymbolAddress((void**)&vh, g_Vh);   cudaGetSymbolAddress((void**)&vl, g_Vl);
    cudaGetSymbolAddress((void**)&ah, g_Ah);   cudaGetSymbolAddress((void**)&al, g_Al);

    cudaFuncSetAttribute(attn_mma3,
                         cudaFuncAttributeMaxDynamicSharedMemorySize, 110592);
    cudaFuncSetAttribute(proj_all,
                         cudaFuncAttributeMaxDynamicSharedMemorySize, 81920);
    cudaFuncSetAttribute(hgemm_out,
                         cudaFuncAttributeMaxDynamicSharedMemorySize, 81920);

    dim3 blk(256);

    // one fused conversion launch (x | ctx | Wq | Wo | Wk | Wv segments)
    convert_all<<<13824, blk>>>(x, ctx, Wq, Wk, Wv, Wo,
                                xh, xl, ch, cl, wqh, wql, wkh, wkl,
                                wvh, wvl, woh, wol);

    // one fused QKV projection launch (Q: 512 CTAs | K: 128 | V: 128)
    proj_all<<<768, blk, 81920>>>(xh, xl, ch, cl, wqh, wql, wkh, wkl,
                                  wvh, wvl, qh, ql, kh, kl, vh, vl);

    attn_mma3<<<dim3(NQ / 128, HEADS, BATCH), blk, 110592>>>(
        qh, ql, kh, kl, vh, vl, ah, al);

    hgemm_out<<<dim3(4, (BATCH * NQ) / 128), blk, 81920>>>(
        ah, al, woh, wol, out, INNER, bo);

    (void)in_sizes; (void)n_in; (void)out_size;
}